// round 12
// baseline (speedup 1.0000x reference)
#include <cuda_runtime.h>
#include <math.h>

#define HH 512
#define WW 512
#define PLANE (512*512)
#define SHAPE_OFF (1*PLANE)
#define SIZE_OFF  (1025*PLANE)
#define HEAT_OFF  (1027*PLANE)
#define NPTS 10
#define MM 128
#define BLKS_PER_HM 64

__device__ unsigned long long g_partial[NPTS][BLKS_PER_HM];
__device__ unsigned int g_arrive[NPTS];   // self-resetting
__device__ unsigned int g_depart[NPTS];   // self-resetting

__device__ __forceinline__ unsigned int fkey(float v) {
    unsigned int b = __float_as_uint(v);
    return (b & 0x80000000u) ? ~b : (b | 0x80000000u);
}
__device__ __forceinline__ unsigned long long umax64(unsigned long long a,
                                                     unsigned long long b) {
    return a > b ? a : b;
}

// 640 blocks (64/heatmap) x 256 threads, single wave.
// Phase 1: scan 16KB chunk -> packed partial; publish with release-atomic.
// Per-heatmap acquire-spin barrier (no threadfence -> no CCTL.IVALL flush).
// Phase 2: reduce 64 partials locally, compute 2 output rows per block.
__global__ void __launch_bounds__(256)
fused_kernel(const float* __restrict__ feat, float* __restrict__ out) {
    __shared__ unsigned long long s[64];
    __shared__ float s_v[2][2][32];   // [row-half][y0/y1][x]
    __shared__ int4 s_meta;

    int hm    = blockIdx.x >> 6;
    int chunk = blockIdx.x & 63;
    const float* heat = feat + HEAT_OFF + (size_t)hm * PLANE;
    int base = chunk * 4096;
    int tid = threadIdx.x;

    // ---- phase 1: chunk argmax (16 floats/thread via 4x float4) ----
    float bestv = -__int_as_float(0x7F800000);  // -inf
    int   bestq = base;
    float4 bq = make_float4(bestv, bestv, bestv, bestv);
#pragma unroll
    for (int j = 0; j < 4; j++) {
        int e = base + ((j * 256 + tid) << 2);
        float4 v = *reinterpret_cast<const float4*>(heat + e);
        float m = fmaxf(fmaxf(v.x, v.y), fmaxf(v.z, v.w));
        if (m > bestv) { bestv = m; bestq = e; bq = v; }  // strict >: first quad wins
    }
    int off4 = (bq.x == bestv) ? 0 : (bq.y == bestv) ? 1 : (bq.z == bestv) ? 2 : 3;
    unsigned long long best =
        ((unsigned long long)fkey(bestv) << 32) |
        (unsigned int)(~(unsigned int)(bestq + off4));

#pragma unroll
    for (int off = 16; off > 0; off >>= 1)
        best = umax64(best, __shfl_xor_sync(0xFFFFFFFFu, best, off));
    if ((tid & 31) == 0) s[tid >> 5] = best;
    __syncthreads();

    if (tid == 0) {
        unsigned long long v = s[0];
#pragma unroll
        for (int i = 1; i < 8; i++) v = umax64(v, s[i]);
        g_partial[hm][chunk] = v;                       // plain store
        // release-increment orders the partial store before the arrival
        asm volatile("red.release.gpu.global.add.u32 [%0], %1;"
                     :: "l"(&g_arrive[hm]), "r"(1u) : "memory");
        // acquire-spin: no L1 flush; g_partial lines were never in our L1
        unsigned int a;
        do {
            asm volatile("ld.acquire.gpu.global.u32 %0, [%1];"
                         : "=r"(a) : "l"(&g_arrive[hm]) : "memory");
        } while (a < BLKS_PER_HM);
        // departure: last block resets both counters for next graph replay
        unsigned int prev;
        asm volatile("atom.acq_rel.gpu.global.add.u32 %0, [%1], %2;"
                     : "=r"(prev) : "l"(&g_depart[hm]), "r"(1u) : "memory");
        if (prev == BLKS_PER_HM - 1) {
            asm volatile("st.relaxed.gpu.global.u32 [%0], %1;"
                         :: "l"(&g_arrive[hm]), "r"(0u) : "memory");
            asm volatile("st.relaxed.gpu.global.u32 [%0], %1;"
                         :: "l"(&g_depart[hm]), "r"(0u) : "memory");
        }
    }
    __syncthreads();

    // ---- phase 2: reduce 64 partials, resolve meta ----
    if (tid < 64) s[tid] = g_partial[hm][tid];
    __syncthreads();
    if (tid < 32) {
        unsigned long long v = umax64(s[tid], s[tid + 32]);
#pragma unroll
        for (int off = 16; off > 0; off >>= 1)
            v = umax64(v, __shfl_xor_sync(0xFFFFFFFFu, v, off));
        if (tid == 0) {
            int idx = (int)(~(unsigned int)(v & 0xFFFFFFFFu));
            float hv = fabsf(feat[SIZE_OFF + idx]);
            float wv = fabsf(feat[SIZE_OFF + PLANE + idx]);
            int h = min(max((int)hv, 1), MM);
            int w = min(max((int)wv, 1), MM);
            s_meta = make_int4(idx, h, w, 0);
        }
    }
    __syncthreads();

    int pbase = s_meta.x;
    int h = s_meta.y, w = s_meta.z;
    int py = pbase >> 9;
    int px = pbase & 511;
    float hf = (float)h, wf = (float)w;

    int half = tid >> 7;          // 0 or 1
    int c    = tid & 127;         // column
    int r    = chunk * 2 + half;  // output row

    float sy = ((float)r + 0.5f) * 32.0f / hf - 0.5f;
    sy = fminf(fmaxf(sy, 0.0f), 31.0f);
    int y0 = (int)floorf(sy);
    int y1 = min(y0 + 1, 31);
    float wy = sy - (float)y0;

    // saliency load: independent of shape gathers -> issued before barrier
    int gr = py - (h >> 1) + r;
    int gc = px - (w >> 1) + c;
    bool valid = (r < h) && (c < w) &&
                 (gr >= 0) && (gr < HH) && (gc >= 0) && (gc < WW);
    float sal = valid ? feat[gr * WW + gc] : 0.0f;

    // shape row gathers (64 scattered loads per half, parallel with sal)
    if (c < 32) {
        s_v[half][0][c] = feat[SHAPE_OFF + (size_t)(y0 * 32 + c) * PLANE + pbase];
    } else if (c < 64) {
        int x = c - 32;
        s_v[half][1][x] = feat[SHAPE_OFF + (size_t)(y1 * 32 + x) * PLANE + pbase];
    }
    __syncthreads();

    float sx = ((float)c + 0.5f) * 32.0f / wf - 0.5f;
    sx = fminf(fmaxf(sx, 0.0f), 31.0f);
    int x0 = (int)floorf(sx);
    int x1 = min(x0 + 1, 31);
    float wx = sx - (float)x0;

    float a0 = s_v[half][0][x0] * (1.0f - wy) + s_v[half][1][x0] * wy;
    float a1 = s_v[half][0][x1] * (1.0f - wy) + s_v[half][1][x1] * wy;
    float v = a0 * (1.0f - wx) + a1 * wx;
    float lv = 1.0f / (1.0f + __expf(-v));

    out[(size_t)hm * (MM * MM) + (size_t)r * MM + c] = valid ? lv * sal : 0.0f;
}

extern "C" void kernel_launch(void* const* d_in, const int* in_sizes, int n_in,
                              void* d_out, int out_size) {
    const float* feat = (const float*)d_in[0];
    float* out = (float*)d_out;
    fused_kernel<<<NPTS * BLKS_PER_HM, 256>>>(feat, out);
}

// round 13
// speedup vs baseline: 1.2250x; 1.2250x over previous
#include <cuda_runtime.h>
#include <math.h>

#define HH 512
#define WW 512
#define PLANE (512*512)
#define SHAPE_OFF (1*PLANE)
#define SIZE_OFF  (1025*PLANE)
#define HEAT_OFF  (1027*PLANE)
#define NPTS 10
#define MM 128
#define BLKS_PER_HM 32
#define ROWS_PER_BLK 4

// per-block partial argmax results; every slot written every run -> no init
__device__ unsigned long long g_partial[NPTS][BLKS_PER_HM];

__device__ __forceinline__ unsigned int fkey(float v) {
    unsigned int b = __float_as_uint(v);
    return (b & 0x80000000u) ? ~b : (b | 0x80000000u);
}
__device__ __forceinline__ unsigned long long umax64(unsigned long long a,
                                                     unsigned long long b) {
    return a > b ? a : b;
}

// 320 blocks (32/heatmap) x 256 threads; 32 floats/thread via 8x float4.
__global__ void __launch_bounds__(256) argmax_kernel(const float* __restrict__ feat) {
    int hm    = blockIdx.x >> 5;
    int chunk = blockIdx.x & 31;
    const float* heat = feat + HEAT_OFF + (size_t)hm * PLANE;
    int base = chunk * 8192;
    int tid = threadIdx.x;

    float bestv = -__int_as_float(0x7F800000);  // -inf
    int   bestq = base;
    float4 bq = make_float4(bestv, bestv, bestv, bestv);

#pragma unroll
    for (int j = 0; j < 8; j++) {
        int e = base + ((j * 256 + tid) << 2);
        float4 v = *reinterpret_cast<const float4*>(heat + e);
        float m = fmaxf(fmaxf(v.x, v.y), fmaxf(v.z, v.w));
        // strict > : on ties the EARLIER quad is kept (e strictly increases)
        if (m > bestv) { bestv = m; bestq = e; bq = v; }
    }

    // first element in winning quad equal to bestv -> global first occurrence
    int off4 = (bq.x == bestv) ? 0 : (bq.y == bestv) ? 1 : (bq.z == bestv) ? 2 : 3;
    int bestidx = bestq + off4;

    unsigned long long best =
        ((unsigned long long)fkey(bestv) << 32) |
        (unsigned int)(~(unsigned int)bestidx);

#pragma unroll
    for (int off = 16; off > 0; off >>= 1)
        best = umax64(best, __shfl_xor_sync(0xFFFFFFFFu, best, off));

    __shared__ unsigned long long s[8];
    if ((tid & 31) == 0) s[tid >> 5] = best;
    __syncthreads();
    if (tid < 32) {
        unsigned long long v = (tid < 8) ? s[tid] : 0ULL;
#pragma unroll
        for (int off = 4; off > 0; off >>= 1)
            v = umax64(v, __shfl_xor_sync(0xFFFFFFFFu, v, off));
        if (tid == 0) g_partial[hm][chunk] = v;
    }
}

// grid (NPTS, 32): one block per 4 output rows, 256 threads.
// Warp 0: load partial + SPECULATIVE size loads for own candidate, shuffle-max
// overlapped with the size loads, unique winner lane writes meta.
// Then: {saliency (2/thr) || shape gathers (1/thr)} -> bilinear -> store.
__global__ void __launch_bounds__(256) compute_kernel(const float* __restrict__ feat,
                                                      float* __restrict__ out) {
    __shared__ float s_v[ROWS_PER_BLK][2][32];   // raw vec rows [rl][y0/y1][x]
    __shared__ int4 s_meta;

    int pt  = blockIdx.x;
    int tid = threadIdx.x;

    if (tid < 32) {
        unsigned long long v = g_partial[pt][tid];
        // speculative: sizes for MY candidate, in flight during the reduce
        int idxj = (int)(~(unsigned int)(v & 0xFFFFFFFFu));
        float hv = fabsf(feat[SIZE_OFF + idxj]);
        float wv = fabsf(feat[SIZE_OFF + PLANE + idxj]);
        unsigned long long m = v;
#pragma unroll
        for (int off = 16; off > 0; off >>= 1)
            m = umax64(m, __shfl_xor_sync(0xFFFFFFFFu, m, off));
        // packed keys are unique (disjoint idx ranges) -> exactly one lane wins
        if (v == m) {
            int h = min(max((int)hv, 1), MM);
            int w = min(max((int)wv, 1), MM);
            s_meta = make_int4(idxj, h, w, 0);
        }
    }
    __syncthreads();

    int pbase = s_meta.x;
    int h = s_meta.y, w = s_meta.z;
    int py = pbase >> 9;
    int px = pbase & 511;
    float hf = (float)h, wf = (float)w;
    int r0 = blockIdx.y * ROWS_PER_BLK;

    // saliency loads (depend only on meta): 2 per thread, issued pre-barrier
    float sal[2];
    bool vmask[2];
#pragma unroll
    for (int k = 0; k < 2; k++) {
        int i = k * 256 + tid;          // 0..511
        int r = r0 + (i >> 7);
        int c = i & 127;
        int gr = py - (h >> 1) + r;
        int gc = px - (w >> 1) + c;
        bool valid = (r < h) && (c < w) &&
                     (gr >= 0) && (gr < HH) && (gc >= 0) && (gc < WW);
        vmask[k] = valid;
        sal[k] = valid ? feat[gr * WW + gc] : 0.0f;
    }

    // shape gathers: exactly 1 per thread (4 rows x {y0,y1} x 32 cols)
    {
        int rl  = tid >> 6;          // 0..3
        int sel = (tid >> 5) & 1;    // 0 -> y0 row, 1 -> y1 row
        int x   = tid & 31;
        float sy = ((float)(r0 + rl) + 0.5f) * 32.0f / hf - 0.5f;
        sy = fminf(fmaxf(sy, 0.0f), 31.0f);
        int y0 = (int)floorf(sy);
        int yy = sel ? min(y0 + 1, 31) : y0;
        s_v[rl][sel][x] = feat[SHAPE_OFF + (size_t)(yy * 32 + x) * PLANE + pbase];
    }
    __syncthreads();

    float* o = out + (size_t)pt * (MM * MM) + (size_t)r0 * MM;
#pragma unroll
    for (int k = 0; k < 2; k++) {
        int i = k * 256 + tid;          // 0..511
        int rl = i >> 7;
        int c  = i & 127;
        float sy = ((float)(r0 + rl) + 0.5f) * 32.0f / hf - 0.5f;
        sy = fminf(fmaxf(sy, 0.0f), 31.0f);
        int y0i = (int)floorf(sy);
        float wy = sy - (float)y0i;
        float sx = ((float)c + 0.5f) * 32.0f / wf - 0.5f;
        sx = fminf(fmaxf(sx, 0.0f), 31.0f);
        int x0 = (int)floorf(sx);
        int x1 = min(x0 + 1, 31);
        float wx = sx - (float)x0;

        float a0 = s_v[rl][0][x0] * (1.0f - wy) + s_v[rl][1][x0] * wy;
        float a1 = s_v[rl][0][x1] * (1.0f - wy) + s_v[rl][1][x1] * wy;
        float v = a0 * (1.0f - wx) + a1 * wx;
        float lv = 1.0f / (1.0f + __expf(-v));
        o[i] = vmask[k] ? lv * sal[k] : 0.0f;
    }
}

extern "C" void kernel_launch(void* const* d_in, const int* in_sizes, int n_in,
                              void* d_out, int out_size) {
    const float* feat = (const float*)d_in[0];
    float* out = (float*)d_out;
    argmax_kernel<<<NPTS * BLKS_PER_HM, 256>>>(feat);
    dim3 g(NPTS, MM / ROWS_PER_BLK);
    compute_kernel<<<g, 256>>>(feat, out);
}

// round 14
// speedup vs baseline: 1.2657x; 1.0332x over previous
#include <cuda_runtime.h>
#include <math.h>

#define HH 512
#define WW 512
#define PLANE (512*512)
#define SHAPE_OFF (1*PLANE)
#define SIZE_OFF  (1025*PLANE)
#define HEAT_OFF  (1027*PLANE)
#define NPTS 10
#define MM 128
#define BLKS_PER_HM 32

// per-block partial argmax results; every slot written every run -> no init
__device__ unsigned long long g_partial[NPTS][BLKS_PER_HM];

__device__ __forceinline__ unsigned int fkey(float v) {
    unsigned int b = __float_as_uint(v);
    return (b & 0x80000000u) ? ~b : (b | 0x80000000u);
}
__device__ __forceinline__ unsigned long long umax64(unsigned long long a,
                                                     unsigned long long b) {
    return a > b ? a : b;
}

// 320 blocks (32/heatmap) x 256 threads; 32 floats/thread via 8x float4.
// FMNMX-tree per quad + rarely-taken update branch; exact first-occurrence
// index resolved once per thread after the loop.
__global__ void __launch_bounds__(256) argmax_kernel(const float* __restrict__ feat) {
    int hm    = blockIdx.x >> 5;
    int chunk = blockIdx.x & 31;
    const float* heat = feat + HEAT_OFF + (size_t)hm * PLANE;
    int base = chunk * 8192;
    int tid = threadIdx.x;

    float bestv = -__int_as_float(0x7F800000);  // -inf
    int   bestq = base;
    float4 bq = make_float4(bestv, bestv, bestv, bestv);

#pragma unroll
    for (int j = 0; j < 8; j++) {
        int e = base + ((j * 256 + tid) << 2);
        float4 v = *reinterpret_cast<const float4*>(heat + e);
        float m = fmaxf(fmaxf(v.x, v.y), fmaxf(v.z, v.w));
        // strict > : on ties the EARLIER quad is kept (e strictly increases)
        if (m > bestv) { bestv = m; bestq = e; bq = v; }
    }

    // first element in winning quad equal to bestv -> global first occurrence
    int off4 = (bq.x == bestv) ? 0 : (bq.y == bestv) ? 1 : (bq.z == bestv) ? 2 : 3;
    int bestidx = bestq + off4;

    unsigned long long best =
        ((unsigned long long)fkey(bestv) << 32) |
        (unsigned int)(~(unsigned int)bestidx);

#pragma unroll
    for (int off = 16; off > 0; off >>= 1)
        best = umax64(best, __shfl_xor_sync(0xFFFFFFFFu, best, off));

    __shared__ unsigned long long s[8];
    if ((tid & 31) == 0) s[tid >> 5] = best;
    __syncthreads();
    if (tid < 32) {
        unsigned long long v = (tid < 8) ? s[tid] : 0ULL;
#pragma unroll
        for (int off = 4; off > 0; off >>= 1)
            v = umax64(v, __shfl_xor_sync(0xFFFFFFFFu, v, off));
        if (tid == 0) g_partial[hm][chunk] = v;
    }
}

// grid (NPTS, 64): one block per 2 output rows, 256 threads = one elem each.
// Warp 0: partial load + SPECULATIVE size loads for own candidate (in flight
// during the shuffle-max); unique winner lane writes meta.
// Then: {saliency || shape row gathers} in parallel -> bilinear -> store.
__global__ void __launch_bounds__(256) compute_kernel(const float* __restrict__ feat,
                                                      float* __restrict__ out) {
    __shared__ float s_v[2][2][32];   // [row-half][y0/y1][x]
    __shared__ int4 s_meta;

    int pt  = blockIdx.x;
    int tid = threadIdx.x;

    if (tid < 32) {
        unsigned long long v = g_partial[pt][tid];
        // speculative size loads for MY candidate, overlapped with the reduce
        int idxj = (int)(~(unsigned int)(v & 0xFFFFFFFFu));
        float hv = fabsf(feat[SIZE_OFF + idxj]);
        float wv = fabsf(feat[SIZE_OFF + PLANE + idxj]);
        unsigned long long m = v;
#pragma unroll
        for (int off = 16; off > 0; off >>= 1)
            m = umax64(m, __shfl_xor_sync(0xFFFFFFFFu, m, off));
        // packed keys are unique (disjoint idx ranges) -> exactly one lane wins
        if (v == m) {
            int h = min(max((int)hv, 1), MM);
            int w = min(max((int)wv, 1), MM);
            s_meta = make_int4(idxj, h, w, 0);
        }
    }
    __syncthreads();

    int pbase = s_meta.x;
    int h = s_meta.y, w = s_meta.z;
    int py = pbase >> 9;
    int px = pbase & 511;
    float hf = (float)h, wf = (float)w;

    int half = tid >> 7;               // 0 or 1
    int c    = tid & 127;              // column
    int r    = blockIdx.y * 2 + half;  // output row

    float sy = ((float)r + 0.5f) * 32.0f / hf - 0.5f;
    sy = fminf(fmaxf(sy, 0.0f), 31.0f);
    int y0 = (int)floorf(sy);
    int y1 = min(y0 + 1, 31);
    float wy = sy - (float)y0;

    // saliency load: independent of shape gathers -> issued before barrier
    int gr = py - (h >> 1) + r;
    int gc = px - (w >> 1) + c;
    bool valid = (r < h) && (c < w) &&
                 (gr >= 0) && (gr < HH) && (gc >= 0) && (gc < WW);
    float sal = valid ? feat[gr * WW + gc] : 0.0f;

    // shape row gathers (64 scattered loads per half, parallel with sal)
    if (c < 32) {
        s_v[half][0][c] = feat[SHAPE_OFF + (size_t)(y0 * 32 + c) * PLANE + pbase];
    } else if (c < 64) {
        int x = c - 32;
        s_v[half][1][x] = feat[SHAPE_OFF + (size_t)(y1 * 32 + x) * PLANE + pbase];
    }
    __syncthreads();

    float sx = ((float)c + 0.5f) * 32.0f / wf - 0.5f;
    sx = fminf(fmaxf(sx, 0.0f), 31.0f);
    int x0 = (int)floorf(sx);
    int x1 = min(x0 + 1, 31);
    float wx = sx - (float)x0;

    float a0 = s_v[half][0][x0] * (1.0f - wy) + s_v[half][1][x0] * wy;
    float a1 = s_v[half][0][x1] * (1.0f - wy) + s_v[half][1][x1] * wy;
    float v = a0 * (1.0f - wx) + a1 * wx;
    float lv = 1.0f / (1.0f + __expf(-v));

    out[(size_t)pt * (MM * MM) + (size_t)r * MM + c] = valid ? lv * sal : 0.0f;
}

extern "C" void kernel_launch(void* const* d_in, const int* in_sizes, int n_in,
                              void* d_out, int out_size) {
    const float* feat = (const float*)d_in[0];
    float* out = (float*)d_out;
    argmax_kernel<<<NPTS * BLKS_PER_HM, 256>>>(feat);
    dim3 g(NPTS, MM / 2);
    compute_kernel<<<g, 256>>>(feat, out);
}